// round 16
// baseline (speedup 1.0000x reference)
#include <cuda_runtime.h>
#include <cuda_fp16.h>
#include <cstdint>

// SPIL layer pipeline, R16 = R12 skeleton (best: 168.4us) + instruction cuts.
//   k_pre : stage theta/phi/z -> fp16  |  s_i per point       [R12-verbatim]
//   aux<0>: g_feat = relu(cf @ phi_w + b)       [NOW single-pass fp16]
//   k1_rl : r_l per (n,k) masked+relu'd                       [R12-verbatim]
//   main  : single-pass fp16 K-split HMMA + softmax + agg     [f32x2 agg, STS.128 conv]
//   aux<1>: out = g_agg @ z_w + g_sumw * z_b    [NOW single-pass fp16]
// R13-R15 lesson: phase-structure changes don't move the wall; main is
// warp-instruction-issue bound (46M warp-instr @ 1.34 IPC = 132us). Cut
// instructions + spend remaining error budget (3.16e-4 of 1e-3).

#define BB 8
#define NN 4096
#define KK 32
#define CC 128
#define HH 64
#define PP 32
#define PTS 4
#define ROWS 128
#define D_THR 0.04f
#define NPTS (BB*NN)        // 32768

__device__ float g_feat[NPTS * HH];
__device__ float g_si[NPTS];
__device__ float g_rl[NPTS * KK];
__device__ float g_agg[NPTS * CC];
__device__ float g_sumw[NPTS];
#define B_STR 72
__device__ __align__(16) __half g_thB[CC * B_STR];
__device__ __align__(16) __half g_phB[CC * B_STR];
__device__ __align__(16) __half g_zB [CC * B_STR];

#define A_STR 136
// ---- aux smem layout (single fp16 A now) ----
#define AX_A   0
#define AX_B   (AX_A + ROWS * A_STR * 2)       // 34816
#define AX_FLT (AX_B + CC * B_STR * 2)         // 53248
#define AX_TOTAL (AX_FLT + 448 * 4)            // 55040
#define F_BIAS 0
#define F_SUMW 64
// ---- main smem layout (single fp16 A) ----
#define MN_A   0
#define MN_B   (MN_A + ROWS * A_STR * 2)       // 34816
#define MN_FLT (MN_B + CC * B_STR * 2)         // 53248
#define F_FEAT 0      // 256 floats
#define F_RF   256    // 128
#define F_THB  384    // 64
#define MN_TOTAL (MN_FLT + 448 * 4)            // 55040

typedef unsigned long long ull;
__device__ __forceinline__ ull pack2(float lo, float hi) {
    ull r;
    asm("mov.b64 %0, {%1,%2};" : "=l"(r) : "f"(lo), "f"(hi));
    return r;
}
__device__ __forceinline__ void unpack2(ull v, float& lo, float& hi) {
    asm("mov.b64 {%0,%1}, %2;" : "=f"(lo), "=f"(hi) : "l"(v));
}
__device__ __forceinline__ ull fma2(ull a, ull b, ull c) {
    ull d;
    asm("fma.rn.f32x2 %0, %1, %2, %3;" : "=l"(d) : "l"(a), "l"(b), "l"(c));
    return d;
}
__device__ __forceinline__ uint32_t smem_to_u32(const void* p) {
    uint32_t a;
    asm("{ .reg .u64 t; cvta.to.shared.u64 t, %1; cvt.u32.u64 %0, t; }" : "=r"(a) : "l"(p));
    return a;
}
__device__ __forceinline__ void ldsm_x4(uint32_t* r, uint32_t addr) {
    asm volatile("ldmatrix.sync.aligned.m8n8.x4.shared.b16 {%0,%1,%2,%3}, [%4];"
                 : "=r"(r[0]), "=r"(r[1]), "=r"(r[2]), "=r"(r[3]) : "r"(addr));
}
__device__ __forceinline__ void ldsm_x4_t(uint32_t* r, uint32_t addr) {
    asm volatile("ldmatrix.sync.aligned.m8n8.x4.trans.shared.b16 {%0,%1,%2,%3}, [%4];"
                 : "=r"(r[0]), "=r"(r[1]), "=r"(r[2]), "=r"(r[3]) : "r"(addr));
}
__device__ __forceinline__ void mma16816(float* d, const uint32_t* a, const uint32_t* b) {
    asm volatile("mma.sync.aligned.m16n8k16.row.col.f32.f16.f16.f32 "
                 "{%0,%1,%2,%3}, {%4,%5,%6,%7}, {%8,%9}, {%0,%1,%2,%3};"
                 : "+f"(d[0]), "+f"(d[1]), "+f"(d[2]), "+f"(d[3])
                 : "r"(a[0]), "r"(a[1]), "r"(a[2]), "r"(a[3]), "r"(b[0]), "r"(b[1]));
}

// ---- A convert to single fp16, STS.128 (ITERS = rows*128/(8*256)) ----
template <int ITERS>
__device__ __forceinline__ void conv_A(const float* __restrict__ src,
                                       char* sA, int tid) {
    const float4* ag = (const float4*)src;
    #pragma unroll
    for (int it = 0; it < ITERS; ++it) {
        int v8 = it * 256 + tid;
        float4 a = __ldg(&ag[2 * v8]);
        float4 b = __ldg(&ag[2 * v8 + 1]);
        int flat = v8 * 8;
        int row = flat >> 7, c = flat & 127;
        __half2 h01 = __float22half2_rn(make_float2(a.x, a.y));
        __half2 h23 = __float22half2_rn(make_float2(a.z, a.w));
        __half2 h45 = __float22half2_rn(make_float2(b.x, b.y));
        __half2 h67 = __float22half2_rn(make_float2(b.z, b.w));
        uint4 u;
        u.x = *(uint32_t*)&h01;
        u.y = *(uint32_t*)&h23;
        u.z = *(uint32_t*)&h45;
        u.w = *(uint32_t*)&h67;
        *(uint4*)(sA + (uint32_t)(row * A_STR + c) * 2) = u;
    }
}

// ---- K-split single-pass GEMM core + 2-round smem D-reduction ----
// After return, khalf=0 warps hold full D (2 m-tiles x 8 n-tiles).
__device__ __forceinline__ void gemm_core(uint32_t aBase, uint32_t bBase,
                                          uint32_t stageBase, int p_w, int khalf,
                                          int lid, float acc[2][8][4]) {
    #pragma unroll
    for (int mt = 0; mt < 2; ++mt)
        #pragma unroll
        for (int nt = 0; nt < 8; ++nt)
            #pragma unroll
            for (int e = 0; e < 4; ++e) acc[mt][nt][e] = 0.f;

    const uint32_t a_row  = (uint32_t)(p_w * 32 + (lid & 15));
    const uint32_t a_colq = (uint32_t)((lid >> 4) * 8);
    const uint32_t aoff   = (a_row * A_STR + a_colq) * 2;
    const uint32_t b_rowl = (uint32_t)(lid & 15);
    const uint32_t b_colq = (uint32_t)((lid >> 4) * 8);

    #pragma unroll
    for (int j = 0; j < 4; ++j) {
        const int kc = 4 * khalf + j;
        uint32_t ah[2][4];
        ldsm_x4(ah[0], aBase + aoff + (uint32_t)(kc * 32));
        ldsm_x4(ah[1], aBase + aoff + (uint32_t)(kc * 32) + 16 * A_STR * 2);

        uint32_t brow = (uint32_t)(kc * 16) + b_rowl;
        uint32_t bh[8][2];
        #pragma unroll
        for (int p = 0; p < 4; ++p) {
            uint32_t bo = (brow * B_STR + 16 * p + b_colq) * 2;
            uint32_t r[4];
            ldsm_x4_t(r, bBase + bo);
            bh[2*p][0] = r[0]; bh[2*p][1] = r[1]; bh[2*p+1][0] = r[2]; bh[2*p+1][1] = r[3];
        }
        #pragma unroll
        for (int mt = 0; mt < 2; ++mt)
            #pragma unroll
            for (int nt = 0; nt < 8; ++nt)
                mma16816(acc[mt][nt], ah[mt], bh[nt]);
    }
    __syncthreads();   // all B ldsm done -> B region (18KB) becomes D staging

    // 2-round K reduction: 4 slots x 4KB = 16KB staged in dead B region
    uint32_t stage = stageBase + (uint32_t)(p_w * 4096) + (uint32_t)(lid * 16);
    #pragma unroll
    for (int mt = 0; mt < 2; ++mt) {
        if (khalf == 1) {
            #pragma unroll
            for (int nt = 0; nt < 8; ++nt)
                asm volatile("st.shared.v4.f32 [%0], {%1,%2,%3,%4};"
                             :: "r"(stage + nt * 512),
                                "f"(acc[mt][nt][0]), "f"(acc[mt][nt][1]),
                                "f"(acc[mt][nt][2]), "f"(acc[mt][nt][3]) : "memory");
        }
        __syncthreads();
        if (khalf == 0) {
            #pragma unroll
            for (int nt = 0; nt < 8; ++nt) {
                float p0, p1, p2, p3;
                asm volatile("ld.shared.v4.f32 {%0,%1,%2,%3}, [%4];"
                             : "=f"(p0), "=f"(p1), "=f"(p2), "=f"(p3)
                             : "r"(stage + nt * 512));
                acc[mt][nt][0] += p0; acc[mt][nt][1] += p1;
                acc[mt][nt][2] += p2; acc[mt][nt][3] += p3;
            }
        }
        __syncthreads();
    }
}

// ---------- k_pre: fp16 weight staging (theta/phi/z) + s_i ----------
#define SI_BLKS  (NPTS / 256)    // 128
__global__ void __launch_bounds__(256) k_pre(const float* __restrict__ cxyz,
                                             const float* __restrict__ m1w,
                                             const float* __restrict__ m1b,
                                             const float* __restrict__ psiw,
                                             const float* __restrict__ tw,
                                             const float* __restrict__ phiw,
                                             const float* __restrict__ zw) {
    int blk = blockIdx.x;
    int tid = threadIdx.x;
    if (blk < SI_BLKS) {
        __shared__ float sw[96], sb2[32], sp[32];
        if (tid < 96) sw[tid] = m1w[tid];
        if (tid < 32) { sb2[tid] = m1b[tid]; sp[tid] = psiw[tid]; }
        __syncthreads();
        int id = blk * 256 + tid;
        float x = cxyz[id * 3], y = cxyz[id * 3 + 1], z = cxyz[id * 3 + 2];
        float si = 0.f;
        #pragma unroll
        for (int d = 0; d < PP; ++d) {
            float pi = fmaf(x, sw[d], fmaf(y, sw[32 + d], fmaf(z, sw[64 + d], sb2[d])));
            si = fmaf(fmaxf(pi, 0.f), sp[d], si);
        }
        g_si[id] = si;
        return;
    }
    blk -= SI_BLKS;
    int m = blk >> 5;                 // 0: theta, 1: phi, 2: z
    int id = (blk & 31) * 256 + tid;
    const float* src = (m == 0) ? tw : (m == 1) ? phiw : zw;
    __half* dst = (m == 0) ? g_thB : (m == 1) ? g_phB : g_zB;
    int c = id >> 6, h = id & 63;
    dst[c * B_STR + h] = __float2half_rn(src[id]);
}

// ---------- k1_rl ----------
__global__ void __launch_bounds__(256) k1_rl(const float* __restrict__ cxyz,
                                             const float* __restrict__ nxyz,
                                             const float* __restrict__ m2w,
                                             const float* __restrict__ m2b,
                                             const float* __restrict__ psiw,
                                             const float* __restrict__ psib) {
    __shared__ float sw[96], sb[32], sp[32], spb;
    int tid = threadIdx.x;
    if (tid < 96) sw[tid] = m2w[tid];
    if (tid < 32) { sb[tid] = m2b[tid]; sp[tid] = psiw[32 + tid]; }
    if (tid == 0) spb = psib[0];
    __syncthreads();
    int g = blockIdx.x * 256 + tid;
    int nl = g >> 5;
    float nx = nxyz[g * 3], ny = nxyz[g * 3 + 1], nz = nxyz[g * 3 + 2];
    float cx = cxyz[nl * 3], cy = cxyz[nl * 3 + 1], cz = cxyz[nl * 3 + 2];
    float sj = 0.f;
    #pragma unroll
    for (int d = 0; d < PP; ++d) {
        float pj = fmaf(nx, sw[d], fmaf(ny, sw[32 + d], fmaf(nz, sw[64 + d], sb[d])));
        sj = fmaf(fmaxf(pj, 0.f), sp[d], sj);
    }
    float dx = cx - nx, dy = cy - ny, dz = cz - nz;
    float dist = sqrtf(dx * dx + dy * dy + dz * dz);
    bool masked = (cz == nz) && (dist > D_THR);
    g_rl[g] = fmaxf(g_si[nl] + sj + spb, 0.f) * (masked ? 0.f : 1.f);
}

// ---------- aux HMMA GEMM: single-pass fp16, 128 rows/CTA ----------
// MODE 0: g_feat = relu(cf @ phi_w + bias)
// MODE 1: outp   = g_agg @ z_w + g_sumw[row] * bias
template <int MODE>
__global__ void __launch_bounds__(256, 2)
aux_gemm(const float* __restrict__ Ain, const float* __restrict__ bias,
         float* __restrict__ outparam)
{
    extern __shared__ char smem[];
    const uint32_t sbase = smem_to_u32(smem);
    char* sA = smem + AX_A;
    float* s_f    = (float*)(smem + AX_FLT);
    float* s_bias = s_f + F_BIAS;
    float* s_sumw = s_f + F_SUMW;

    const int tid = threadIdx.x;
    const int wid = tid >> 5;
    const int lid = tid & 31;
    const int p_w   = wid & 3;
    const int khalf = wid >> 2;
    const int r0 = blockIdx.x * 128;

    const float* Asrc = (MODE == 0) ? Ain : g_agg;
    const __half* Bsrc = (MODE == 0) ? g_phB : g_zB;
    float* outp = (MODE == 0) ? g_feat : outparam;

    conv_A<8>(Asrc + (size_t)r0 * CC, sA, tid);
    {
        const uint4* tb = (const uint4*)Bsrc;
        uint4* bd = (uint4*)(smem + AX_B);
        #pragma unroll
        for (int i = tid; i < 1152; i += 256) bd[i] = __ldg(&tb[i]);
        if (tid < 64) s_bias[tid] = bias[tid];
        if (MODE == 1 && tid < 128) s_sumw[tid] = g_sumw[r0 + tid];
    }
    __syncthreads();

    float acc[2][8][4];
    gemm_core(sbase + AX_A, sbase + AX_B, sbase + AX_B, p_w, khalf, lid, acc);

    if (khalf == 0) {
        const int g = lid >> 2, t = lid & 3;
        #pragma unroll
        for (int mt = 0; mt < 2; ++mt) {
            #pragma unroll
            for (int nt = 0; nt < 8; ++nt) {
                int h = nt * 8 + t * 2;
                float b0 = s_bias[h], b1 = s_bias[h + 1];
                int lr0 = p_w * 32 + g + 16 * mt;
                float v00, v01, v10, v11;
                if (MODE == 0) {
                    v00 = fmaxf(acc[mt][nt][0] + b0, 0.f);
                    v01 = fmaxf(acc[mt][nt][1] + b1, 0.f);
                    v10 = fmaxf(acc[mt][nt][2] + b0, 0.f);
                    v11 = fmaxf(acc[mt][nt][3] + b1, 0.f);
                } else {
                    float s0 = s_sumw[lr0], s1 = s_sumw[lr0 + 8];
                    v00 = fmaf(s0, b0, acc[mt][nt][0]);
                    v01 = fmaf(s0, b1, acc[mt][nt][1]);
                    v10 = fmaf(s1, b0, acc[mt][nt][2]);
                    v11 = fmaf(s1, b1, acc[mt][nt][3]);
                }
                *(float2*)&outp[(size_t)(r0 + lr0) * HH + h]     = make_float2(v00, v01);
                *(float2*)&outp[(size_t)(r0 + lr0 + 8) * HH + h] = make_float2(v10, v11);
            }
        }
    }
}

// ---------- main: single-pass fp16 K-split theta GEMM + softmax + aggregation ----------
__global__ void __launch_bounds__(256, 2)
spil_main(const float* __restrict__ neighbor_features,
          const float* __restrict__ theta_b)
{
    extern __shared__ char smem[];
    const uint32_t sbase = smem_to_u32(smem);
    char* sA = smem + MN_A;
    float* s_f    = (float*)(smem + MN_FLT);
    float* s_feat = s_f + F_FEAT;
    float* s_rf   = s_f + F_RF;
    float* s_thb  = s_f + F_THB;

    const int tid = threadIdx.x;
    const int wid = tid >> 5;
    const int lid = tid & 31;
    const int p_w   = wid & 3;
    const int khalf = wid >> 2;
    const int bn0 = blockIdx.x * PTS;

    const float r_l = __ldg(&g_rl[blockIdx.x * 128 + p_w * 32 + lid]);

    conv_A<8>(neighbor_features + (size_t)bn0 * KK * CC, sA, tid);
    {
        const uint4* tb = (const uint4*)g_thB;
        uint4* bd = (uint4*)(smem + MN_B);
        #pragma unroll
        for (int i = tid; i < 1152; i += 256) bd[i] = __ldg(&tb[i]);
        if (tid < 64)
            ((uint4*)s_feat)[tid] = __ldg(&((const uint4*)(g_feat + (size_t)bn0 * HH))[tid]);
        if (tid < 64) s_thb[tid] = theta_b[tid];
    }
    __syncthreads();

    float acc[2][8][4];
    gemm_core(sbase + MN_A, sbase + MN_B, sbase + MN_B, p_w, khalf, lid, acc);

    // r_f reduction (khalf=0 warps, fragment layout)
    if (khalf == 0) {
        const int g = lid >> 2, t = lid & 3;
        const float* fp = s_feat + p_w * HH;
        float r4[4];
        #pragma unroll
        for (int mt = 0; mt < 2; ++mt) {
            float rA = 0.f, rB = 0.f;
            #pragma unroll
            for (int nt = 0; nt < 8; ++nt) {
                int h0 = nt * 8 + t * 2, h1 = h0 + 1;
                float tb0 = s_thb[h0], tb1 = s_thb[h1];
                float f0 = fp[h0], f1 = fp[h1];
                rA = fmaf(fmaxf(acc[mt][nt][0] + tb0, 0.f), f0, rA);
                rA = fmaf(fmaxf(acc[mt][nt][1] + tb1, 0.f), f1, rA);
                rB = fmaf(fmaxf(acc[mt][nt][2] + tb0, 0.f), f0, rB);
                rB = fmaf(fmaxf(acc[mt][nt][3] + tb1, 0.f), f1, rB);
            }
            r4[mt * 2]     = rA;
            r4[mt * 2 + 1] = rB;
        }
        #pragma unroll
        for (int i = 0; i < 4; ++i) {
            r4[i] += __shfl_xor_sync(0xffffffffu, r4[i], 1);
            r4[i] += __shfl_xor_sync(0xffffffffu, r4[i], 2);
        }
        if (t == 0) {
            s_rf[p_w * 32 + g]      = r4[0];
            s_rf[p_w * 32 + g + 8]  = r4[1];
            s_rf[p_w * 32 + g + 16] = r4[2];
            s_rf[p_w * 32 + g + 24] = r4[3];
        }
    }
    __syncthreads();

    // softmax (redundant in both khalf warps of a point)
    float Wk;
    {
        float rf = s_rf[p_w * 32 + lid] * 0.125f;
        float m = rf;
        #pragma unroll
        for (int ofs = 16; ofs > 0; ofs >>= 1) m = fmaxf(m, __shfl_xor_sync(0xffffffffu, m, ofs));
        float e = r_l * __expf(rf - m);
        float s = e;
        #pragma unroll
        for (int ofs = 16; ofs > 0; ofs >>= 1) s += __shfl_xor_sync(0xffffffffu, s, ofs);
        float denom = s + 1e-8f;
        Wk = e / denom;
        if (khalf == 0 && lid == 0) g_sumw[bn0 + p_w] = s / denom;
    }

    // aggregation: warp covers its 64-column half; f32x2 packed FMA
    {
        ull a01 = 0ull;
        const uint32_t co = (uint32_t)(128 * khalf + 4 * lid);
        #pragma unroll
        for (int k = 0; k < KK; ++k) {
            float wk = __shfl_sync(0xffffffffu, Wk, k);
            ull wk2 = pack2(wk, wk);
            uint32_t o = (uint32_t)((p_w * KK + k) * A_STR) * 2 + co;
            float2 h0 = __half22float2(*(__half2*)(sA + o));
            a01 = fma2(wk2, pack2(h0.x, h0.y), a01);
        }
        float r0, r1;
        unpack2(a01, r0, r1);
        float* dst = g_agg + (size_t)(bn0 + p_w) * CC + 64 * khalf;
        *(float2*)&dst[2 * lid] = make_float2(r0, r1);
    }
}

extern "C" void kernel_launch(void* const* d_in, const int* in_sizes, int n_in,
                              void* d_out, int out_size)
{
    (void)in_sizes; (void)n_in; (void)out_size;
    const float* center_xyz        = (const float*)d_in[0];
    const float* center_features   = (const float*)d_in[1];
    const float* neighbor_xyz      = (const float*)d_in[2];
    const float* neighbor_features = (const float*)d_in[3];
    const float* phi_w   = (const float*)d_in[4];
    const float* phi_b   = (const float*)d_in[5];
    const float* theta_w = (const float*)d_in[6];
    const float* theta_b = (const float*)d_in[7];
    const float* m1_w    = (const float*)d_in[8];
    const float* m1_b    = (const float*)d_in[9];
    const float* m2_w    = (const float*)d_in[10];
    const float* m2_b    = (const float*)d_in[11];
    const float* psi_w   = (const float*)d_in[12];
    const float* psi_b   = (const float*)d_in[13];
    const float* z_w     = (const float*)d_in[14];
    const float* z_b     = (const float*)d_in[15];
    float* out = (float*)d_out;

    cudaFuncSetAttribute(spil_main, cudaFuncAttributeMaxDynamicSharedMemorySize, MN_TOTAL);
    cudaFuncSetAttribute(aux_gemm<0>, cudaFuncAttributeMaxDynamicSharedMemorySize, AX_TOTAL);
    cudaFuncSetAttribute(aux_gemm<1>, cudaFuncAttributeMaxDynamicSharedMemorySize, AX_TOTAL);

    k_pre<<<SI_BLKS + 96, 256>>>(center_xyz, m1_w, m1_b, psi_w, theta_w, phi_w, z_w);
    aux_gemm<0><<<NPTS / 128, 256, AX_TOTAL>>>(center_features, phi_b, out);
    k1_rl<<<NPTS * KK / 256, 256>>>(center_xyz, neighbor_xyz, m2_w, m2_b, psi_w, psi_b);
    spil_main<<<NPTS / PTS, 256, MN_TOTAL>>>(neighbor_features, theta_b);
    aux_gemm<1><<<NPTS / 128, 256, AX_TOTAL>>>(center_features, z_b, out);
}

// round 17
// speedup vs baseline: 1.0841x; 1.0841x over previous
#include <cuda_runtime.h>
#include <cuda_fp16.h>
#include <cstdint>

// SPIL layer pipeline, R17 = R12 verbatim (best: 168.4us) + stream overlap.
// DAG: k_pre -> {aux<0> || k1_rl} -> main -> aux<1>. aux<0> (11us) and k1_rl
// (16us) are independent, low-utilization kernels -> run aux<0> on a second
// stream (event fork-join; graph-capturable) to hide ~11us.
// R16 lesson: main micro-opts (STS.128 conv, f32x2 agg) regressed codegen;
// aux instruction cuts don't matter (aux is wave-latency bound at 256 CTAs).
// All kernels below are byte-identical to R12.

#define BB 8
#define NN 4096
#define KK 32
#define CC 128
#define HH 64
#define PP 32
#define PTS 4
#define ROWS 128
#define D_THR 0.04f
#define NPTS (BB*NN)        // 32768

__device__ float g_feat[NPTS * HH];
__device__ float g_si[NPTS];
__device__ float g_rl[NPTS * KK];
__device__ float g_agg[NPTS * CC];
__device__ float g_sumw[NPTS];
#define B_STR 72
__device__ __align__(16) __half g_thB[CC * B_STR];
__device__ __align__(16) __half g_phB[CC * B_STR];
__device__ __align__(16) __half g_zB [CC * B_STR];

#define A_STR 136
// ---- aux smem layout (R12: A hi/lo 2-pass) ----
#define AX_A_HI 0
#define AX_A_LO (AX_A_HI + ROWS * A_STR * 2)   // 34816
#define AX_B    (AX_A_LO + ROWS * A_STR * 2)   // 69632
#define AX_FLT  (AX_B + CC * B_STR * 2)        // 88064
#define AX_TOTAL (AX_FLT + 448 * 4)            // 89856
#define F_BIAS 0
#define F_SUMW 64
// ---- main smem layout (single fp16 A) ----
#define MN_A   0
#define MN_B   (MN_A + ROWS * A_STR * 2)       // 34816
#define MN_FLT (MN_B + CC * B_STR * 2)         // 53248
#define F_FEAT 0      // 256 floats
#define F_RF   256    // 128
#define F_THB  384    // 64
#define MN_TOTAL (MN_FLT + 448 * 4)            // 55040

__device__ __forceinline__ uint32_t smem_to_u32(const void* p) {
    uint32_t a;
    asm("{ .reg .u64 t; cvta.to.shared.u64 t, %1; cvt.u32.u64 %0, t; }" : "=r"(a) : "l"(p));
    return a;
}
__device__ __forceinline__ void ldsm_x4(uint32_t* r, uint32_t addr) {
    asm volatile("ldmatrix.sync.aligned.m8n8.x4.shared.b16 {%0,%1,%2,%3}, [%4];"
                 : "=r"(r[0]), "=r"(r[1]), "=r"(r[2]), "=r"(r[3]) : "r"(addr));
}
__device__ __forceinline__ void ldsm_x4_t(uint32_t* r, uint32_t addr) {
    asm volatile("ldmatrix.sync.aligned.m8n8.x4.trans.shared.b16 {%0,%1,%2,%3}, [%4];"
                 : "=r"(r[0]), "=r"(r[1]), "=r"(r[2]), "=r"(r[3]) : "r"(addr));
}
__device__ __forceinline__ void mma16816(float* d, const uint32_t* a, const uint32_t* b) {
    asm volatile("mma.sync.aligned.m16n8k16.row.col.f32.f16.f16.f32 "
                 "{%0,%1,%2,%3}, {%4,%5,%6,%7}, {%8,%9}, {%0,%1,%2,%3};"
                 : "+f"(d[0]), "+f"(d[1]), "+f"(d[2]), "+f"(d[3])
                 : "r"(a[0]), "r"(a[1]), "r"(a[2]), "r"(a[3]), "r"(b[0]), "r"(b[1]));
}

// ---- A split hi/lo (aux, 2-pass) ----
__device__ __forceinline__ void split_A_hilo(const float* __restrict__ src,
                                             char* sA_hi, char* sA_lo, int tid) {
    const float4* ag = (const float4*)src;
    #pragma unroll
    for (int it = 0; it < 16; ++it) {
        int v4 = it * 256 + tid;
        float4 v = __ldg(&ag[v4]);
        int flat = v4 * 4;
        int row = flat >> 7, c = flat & 127;
        __half2 h01 = __float22half2_rn(make_float2(v.x, v.y));
        __half2 h23 = __float22half2_rn(make_float2(v.z, v.w));
        float2 f01 = __half22float2(h01);
        float2 f23 = __half22float2(h23);
        __half2 l01 = __float22half2_rn(make_float2(v.x - f01.x, v.y - f01.y));
        __half2 l23 = __float22half2_rn(make_float2(v.z - f23.x, v.w - f23.y));
        uint32_t o = (uint32_t)(row * A_STR + c) * 2;
        *(__half2*)(sA_hi + o)     = h01;
        *(__half2*)(sA_hi + o + 4) = h23;
        *(__half2*)(sA_lo + o)     = l01;
        *(__half2*)(sA_lo + o + 4) = l23;
    }
}

// ---- A convert single fp16 (main) ----
__device__ __forceinline__ void conv_A(const float* __restrict__ src,
                                       char* sA, int tid) {
    const float4* ag = (const float4*)src;
    #pragma unroll
    for (int it = 0; it < 16; ++it) {
        int v4 = it * 256 + tid;
        float4 v = __ldg(&ag[v4]);
        int flat = v4 * 4;
        int row = flat >> 7, c = flat & 127;
        __half2 h01 = __float22half2_rn(make_float2(v.x, v.y));
        __half2 h23 = __float22half2_rn(make_float2(v.z, v.w));
        uint2 u;
        u.x = *(uint32_t*)&h01;
        u.y = *(uint32_t*)&h23;
        *(uint2*)(sA + (uint32_t)(row * A_STR + c) * 2) = u;
    }
}

// ---- K-split GEMM core (TWOPASS: + A-lo pass) + 2-round smem D-reduction ----
template <bool TWOPASS>
__device__ __forceinline__ void gemm_core(uint32_t aHi, uint32_t aLo, uint32_t bBase,
                                          uint32_t stageBase, int p_w, int khalf,
                                          int lid, float acc[2][8][4]) {
    #pragma unroll
    for (int mt = 0; mt < 2; ++mt)
        #pragma unroll
        for (int nt = 0; nt < 8; ++nt)
            #pragma unroll
            for (int e = 0; e < 4; ++e) acc[mt][nt][e] = 0.f;

    const uint32_t a_row  = (uint32_t)(p_w * 32 + (lid & 15));
    const uint32_t a_colq = (uint32_t)((lid >> 4) * 8);
    const uint32_t aoff   = (a_row * A_STR + a_colq) * 2;
    const uint32_t b_rowl = (uint32_t)(lid & 15);
    const uint32_t b_colq = (uint32_t)((lid >> 4) * 8);

    #pragma unroll
    for (int j = 0; j < 4; ++j) {
        const int kc = 4 * khalf + j;
        uint32_t ah[2][4], al[2][4];
        ldsm_x4(ah[0], aHi + aoff + (uint32_t)(kc * 32));
        ldsm_x4(ah[1], aHi + aoff + (uint32_t)(kc * 32) + 16 * A_STR * 2);
        if (TWOPASS) {
            ldsm_x4(al[0], aLo + aoff + (uint32_t)(kc * 32));
            ldsm_x4(al[1], aLo + aoff + (uint32_t)(kc * 32) + 16 * A_STR * 2);
        }

        uint32_t brow = (uint32_t)(kc * 16) + b_rowl;
        uint32_t bh[8][2];
        #pragma unroll
        for (int p = 0; p < 4; ++p) {
            uint32_t bo = (brow * B_STR + 16 * p + b_colq) * 2;
            uint32_t r[4];
            ldsm_x4_t(r, bBase + bo);
            bh[2*p][0] = r[0]; bh[2*p][1] = r[1]; bh[2*p+1][0] = r[2]; bh[2*p+1][1] = r[3];
        }
        #pragma unroll
        for (int mt = 0; mt < 2; ++mt)
            #pragma unroll
            for (int nt = 0; nt < 8; ++nt) {
                mma16816(acc[mt][nt], ah[mt], bh[nt]);
                if (TWOPASS) mma16816(acc[mt][nt], al[mt], bh[nt]);
            }
    }
    __syncthreads();   // all B ldsm done -> B region (18KB) becomes D staging

    // 2-round K reduction: 4 slots x 4KB = 16KB staged in dead B region
    uint32_t stage = stageBase + (uint32_t)(p_w * 4096) + (uint32_t)(lid * 16);
    #pragma unroll
    for (int mt = 0; mt < 2; ++mt) {
        if (khalf == 1) {
            #pragma unroll
            for (int nt = 0; nt < 8; ++nt)
                asm volatile("st.shared.v4.f32 [%0], {%1,%2,%3,%4};"
                             :: "r"(stage + nt * 512),
                                "f"(acc[mt][nt][0]), "f"(acc[mt][nt][1]),
                                "f"(acc[mt][nt][2]), "f"(acc[mt][nt][3]) : "memory");
        }
        __syncthreads();
        if (khalf == 0) {
            #pragma unroll
            for (int nt = 0; nt < 8; ++nt) {
                float p0, p1, p2, p3;
                asm volatile("ld.shared.v4.f32 {%0,%1,%2,%3}, [%4];"
                             : "=f"(p0), "=f"(p1), "=f"(p2), "=f"(p3)
                             : "r"(stage + nt * 512));
                acc[mt][nt][0] += p0; acc[mt][nt][1] += p1;
                acc[mt][nt][2] += p2; acc[mt][nt][3] += p3;
            }
        }
        __syncthreads();
    }
}

// ---------- k_pre: fp16 weight staging (theta/phi/z) + s_i ----------
#define SI_BLKS  (NPTS / 256)    // 128
__global__ void __launch_bounds__(256) k_pre(const float* __restrict__ cxyz,
                                             const float* __restrict__ m1w,
                                             const float* __restrict__ m1b,
                                             const float* __restrict__ psiw,
                                             const float* __restrict__ tw,
                                             const float* __restrict__ phiw,
                                             const float* __restrict__ zw) {
    int blk = blockIdx.x;
    int tid = threadIdx.x;
    if (blk < SI_BLKS) {
        __shared__ float sw[96], sb2[32], sp[32];
        if (tid < 96) sw[tid] = m1w[tid];
        if (tid < 32) { sb2[tid] = m1b[tid]; sp[tid] = psiw[tid]; }
        __syncthreads();
        int id = blk * 256 + tid;
        float x = cxyz[id * 3], y = cxyz[id * 3 + 1], z = cxyz[id * 3 + 2];
        float si = 0.f;
        #pragma unroll
        for (int d = 0; d < PP; ++d) {
            float pi = fmaf(x, sw[d], fmaf(y, sw[32 + d], fmaf(z, sw[64 + d], sb2[d])));
            si = fmaf(fmaxf(pi, 0.f), sp[d], si);
        }
        g_si[id] = si;
        return;
    }
    blk -= SI_BLKS;
    int m = blk >> 5;                 // 0: theta, 1: phi, 2: z
    int id = (blk & 31) * 256 + tid;
    const float* src = (m == 0) ? tw : (m == 1) ? phiw : zw;
    __half* dst = (m == 0) ? g_thB : (m == 1) ? g_phB : g_zB;
    int c = id >> 6, h = id & 63;
    dst[c * B_STR + h] = __float2half_rn(src[id]);
}

// ---------- k1_rl ----------
__global__ void __launch_bounds__(256) k1_rl(const float* __restrict__ cxyz,
                                             const float* __restrict__ nxyz,
                                             const float* __restrict__ m2w,
                                             const float* __restrict__ m2b,
                                             const float* __restrict__ psiw,
                                             const float* __restrict__ psib) {
    __shared__ float sw[96], sb[32], sp[32], spb;
    int tid = threadIdx.x;
    if (tid < 96) sw[tid] = m2w[tid];
    if (tid < 32) { sb[tid] = m2b[tid]; sp[tid] = psiw[32 + tid]; }
    if (tid == 0) spb = psib[0];
    __syncthreads();
    int g = blockIdx.x * 256 + tid;
    int nl = g >> 5;
    float nx = nxyz[g * 3], ny = nxyz[g * 3 + 1], nz = nxyz[g * 3 + 2];
    float cx = cxyz[nl * 3], cy = cxyz[nl * 3 + 1], cz = cxyz[nl * 3 + 2];
    float sj = 0.f;
    #pragma unroll
    for (int d = 0; d < PP; ++d) {
        float pj = fmaf(nx, sw[d], fmaf(ny, sw[32 + d], fmaf(nz, sw[64 + d], sb[d])));
        sj = fmaf(fmaxf(pj, 0.f), sp[d], sj);
    }
    float dx = cx - nx, dy = cy - ny, dz = cz - nz;
    float dist = sqrtf(dx * dx + dy * dy + dz * dz);
    bool masked = (cz == nz) && (dist > D_THR);
    g_rl[g] = fmaxf(g_si[nl] + sj + spb, 0.f) * (masked ? 0.f : 1.f);
}

// ---------- aux HMMA GEMM (R12-verbatim, 2-pass A) ----------
// MODE 0: g_feat = relu(cf @ phi_w + bias)
// MODE 1: outp   = g_agg @ z_w + g_sumw[row] * bias
template <int MODE>
__global__ void __launch_bounds__(256, 2)
aux_gemm(const float* __restrict__ Ain, const float* __restrict__ bias,
         float* __restrict__ outparam)
{
    extern __shared__ char smem[];
    const uint32_t sbase = smem_to_u32(smem);
    char* sA_hi = smem + AX_A_HI;
    char* sA_lo = smem + AX_A_LO;
    float* s_f    = (float*)(smem + AX_FLT);
    float* s_bias = s_f + F_BIAS;
    float* s_sumw = s_f + F_SUMW;

    const int tid = threadIdx.x;
    const int wid = tid >> 5;
    const int lid = tid & 31;
    const int p_w   = wid & 3;
    const int khalf = wid >> 2;
    const int r0 = blockIdx.x * 128;

    const float* Asrc = (MODE == 0) ? Ain : g_agg;
    const __half* Bsrc = (MODE == 0) ? g_phB : g_zB;
    float* outp = (MODE == 0) ? g_feat : outparam;

    split_A_hilo(Asrc + (size_t)r0 * CC, sA_hi, sA_lo, tid);
    {
        const uint4* tb = (const uint4*)Bsrc;
        uint4* bd = (uint4*)(smem + AX_B);
        #pragma unroll
        for (int i = tid; i < 1152; i += 256) bd[i] = __ldg(&tb[i]);
        if (tid < 64) s_bias[tid] = bias[tid];
        if (MODE == 1 && tid < 128) s_sumw[tid] = g_sumw[r0 + tid];
    }
    __syncthreads();

    float acc[2][8][4];
    gemm_core<true>(sbase + AX_A_HI, sbase + AX_A_LO, sbase + AX_B,
                    sbase + AX_B, p_w, khalf, lid, acc);

    if (khalf == 0) {
        const int g = lid >> 2, t = lid & 3;
        #pragma unroll
        for (int mt = 0; mt < 2; ++mt) {
            #pragma unroll
            for (int nt = 0; nt < 8; ++nt) {
                int h = nt * 8 + t * 2;
                float b0 = s_bias[h], b1 = s_bias[h + 1];
                int lr0 = p_w * 32 + g + 16 * mt;
                float v00, v01, v10, v11;
                if (MODE == 0) {
                    v00 = fmaxf(acc[mt][nt][0] + b0, 0.f);
                    v01 = fmaxf(acc[mt][nt][1] + b1, 0.f);
                    v10 = fmaxf(acc[mt][nt][2] + b0, 0.f);
                    v11 = fmaxf(acc[mt][nt][3] + b1, 0.f);
                } else {
                    float s0 = s_sumw[lr0], s1 = s_sumw[lr0 + 8];
                    v00 = fmaf(s0, b0, acc[mt][nt][0]);
                    v01 = fmaf(s0, b1, acc[mt][nt][1]);
                    v10 = fmaf(s1, b0, acc[mt][nt][2]);
                    v11 = fmaf(s1, b1, acc[mt][nt][3]);
                }
                *(float2*)&outp[(size_t)(r0 + lr0) * HH + h]     = make_float2(v00, v01);
                *(float2*)&outp[(size_t)(r0 + lr0 + 8) * HH + h] = make_float2(v10, v11);
            }
        }
    }
}

// ---------- main: single-pass fp16 theta GEMM + softmax + aggregation (R12) ----------
__global__ void __launch_bounds__(256, 2)
spil_main(const float* __restrict__ neighbor_features,
          const float* __restrict__ theta_b)
{
    extern __shared__ char smem[];
    const uint32_t sbase = smem_to_u32(smem);
    char* sA = smem + MN_A;
    float* s_f    = (float*)(smem + MN_FLT);
    float* s_feat = s_f + F_FEAT;
    float* s_rf   = s_f + F_RF;
    float* s_thb  = s_f + F_THB;

    const int tid = threadIdx.x;
    const int wid = tid >> 5;
    const int lid = tid & 31;
    const int p_w   = wid & 3;
    const int khalf = wid >> 2;
    const int bn0 = blockIdx.x * PTS;

    const float r_l = __ldg(&g_rl[blockIdx.x * 128 + p_w * 32 + lid]);

    conv_A(neighbor_features + (size_t)bn0 * KK * CC, sA, tid);
    {
        const uint4* tb = (const uint4*)g_thB;
        uint4* bd = (uint4*)(smem + MN_B);
        #pragma unroll
        for (int i = tid; i < 1152; i += 256) bd[i] = __ldg(&tb[i]);
        if (tid < 64)
            ((uint4*)s_feat)[tid] = __ldg(&((const uint4*)(g_feat + (size_t)bn0 * HH))[tid]);
        if (tid < 64) s_thb[tid] = theta_b[tid];
    }
    __syncthreads();

    float acc[2][8][4];
    gemm_core<false>(sbase + MN_A, 0u, sbase + MN_B,
                     sbase + MN_B, p_w, khalf, lid, acc);

    // r_f reduction (khalf=0 warps, fragment layout)
    if (khalf == 0) {
        const int g = lid >> 2, t = lid & 3;
        const float* fp = s_feat + p_w * HH;
        float r4[4];
        #pragma unroll
        for (int mt = 0; mt < 2; ++mt) {
            float rA = 0.f, rB = 0.f;
            #pragma unroll
            for (int nt = 0; nt < 8; ++nt) {
                int h0 = nt * 8 + t * 2, h1 = h0 + 1;
                float tb0 = s_thb[h0], tb1 = s_thb[h1];
                float f0 = fp[h0], f1 = fp[h1];
                rA = fmaf(fmaxf(acc[mt][nt][0] + tb0, 0.f), f0, rA);
                rA = fmaf(fmaxf(acc[mt][nt][1] + tb1, 0.f), f1, rA);
                rB = fmaf(fmaxf(acc[mt][nt][2] + tb0, 0.f), f0, rB);
                rB = fmaf(fmaxf(acc[mt][nt][3] + tb1, 0.f), f1, rB);
            }
            r4[mt * 2]     = rA;
            r4[mt * 2 + 1] = rB;
        }
        #pragma unroll
        for (int i = 0; i < 4; ++i) {
            r4[i] += __shfl_xor_sync(0xffffffffu, r4[i], 1);
            r4[i] += __shfl_xor_sync(0xffffffffu, r4[i], 2);
        }
        if (t == 0) {
            s_rf[p_w * 32 + g]      = r4[0];
            s_rf[p_w * 32 + g + 8]  = r4[1];
            s_rf[p_w * 32 + g + 16] = r4[2];
            s_rf[p_w * 32 + g + 24] = r4[3];
        }
    }
    __syncthreads();

    // softmax (redundant in both khalf warps of a point)
    float Wk;
    {
        float rf = s_rf[p_w * 32 + lid] * 0.125f;
        float m = rf;
        #pragma unroll
        for (int ofs = 16; ofs > 0; ofs >>= 1) m = fmaxf(m, __shfl_xor_sync(0xffffffffu, m, ofs));
        float e = r_l * __expf(rf - m);
        float s = e;
        #pragma unroll
        for (int ofs = 16; ofs > 0; ofs >>= 1) s += __shfl_xor_sync(0xffffffffu, s, ofs);
        float denom = s + 1e-8f;
        Wk = e / denom;
        if (khalf == 0 && lid == 0) g_sumw[bn0 + p_w] = s / denom;
    }

    // aggregation: warp covers its 64-column half (c = 64*khalf + 2*lid, +1), fp16 nf
    {
        float2 a01 = make_float2(0.f, 0.f);
        const uint32_t co = (uint32_t)(128 * khalf + 4 * lid);
        #pragma unroll
        for (int k = 0; k < KK; ++k) {
            float wk = __shfl_sync(0xffffffffu, Wk, k);
            uint32_t o = (uint32_t)((p_w * KK + k) * A_STR) * 2 + co;
            float2 h0 = __half22float2(*(__half2*)(sA + o));
            a01.x = fmaf(wk, h0.x, a01.x);
            a01.y = fmaf(wk, h0.y, a01.y);
        }
        float* dst = g_agg + (size_t)(bn0 + p_w) * CC + 64 * khalf;
        *(float2*)&dst[2 * lid] = a01;
    }
}

extern "C" void kernel_launch(void* const* d_in, const int* in_sizes, int n_in,
                              void* d_out, int out_size)
{
    (void)in_sizes; (void)n_in; (void)out_size;
    const float* center_xyz        = (const float*)d_in[0];
    const float* center_features   = (const float*)d_in[1];
    const float* neighbor_xyz      = (const float*)d_in[2];
    const float* neighbor_features = (const float*)d_in[3];
    const float* phi_w   = (const float*)d_in[4];
    const float* phi_b   = (const float*)d_in[5];
    const float* theta_w = (const float*)d_in[6];
    const float* theta_b = (const float*)d_in[7];
    const float* m1_w    = (const float*)d_in[8];
    const float* m1_b    = (const float*)d_in[9];
    const float* m2_w    = (const float*)d_in[10];
    const float* m2_b    = (const float*)d_in[11];
    const float* psi_w   = (const float*)d_in[12];
    const float* psi_b   = (const float*)d_in[13];
    const float* z_w     = (const float*)d_in[14];
    const float* z_b     = (const float*)d_in[15];
    float* out = (float*)d_out;

    static cudaStream_t s2 = nullptr;
    static cudaEvent_t evFork = nullptr, evJoin = nullptr;
    if (s2 == nullptr) {
        cudaStreamCreateWithFlags(&s2, cudaStreamNonBlocking);
        cudaEventCreateWithFlags(&evFork, cudaEventDisableTiming);
        cudaEventCreateWithFlags(&evJoin, cudaEventDisableTiming);
        cudaFuncSetAttribute(spil_main, cudaFuncAttributeMaxDynamicSharedMemorySize, MN_TOTAL);
        cudaFuncSetAttribute(aux_gemm<0>, cudaFuncAttributeMaxDynamicSharedMemorySize, AX_TOTAL);
        cudaFuncSetAttribute(aux_gemm<1>, cudaFuncAttributeMaxDynamicSharedMemorySize, AX_TOTAL);
    }

    // k_pre on the capture stream
    k_pre<<<SI_BLKS + 96, 256>>>(center_xyz, m1_w, m1_b, psi_w, theta_w, phi_w, z_w);

    // fork: aux<0> on s2, k1_rl on the capture stream (independent of each other)
    cudaEventRecord(evFork, 0);
    cudaStreamWaitEvent(s2, evFork, 0);
    aux_gemm<0><<<NPTS / 128, 256, AX_TOTAL, s2>>>(center_features, phi_b, out);
    k1_rl<<<NPTS * KK / 256, 256>>>(center_xyz, neighbor_xyz, m2_w, m2_b, psi_w, psi_b);
    // join: main depends on both
    cudaEventRecord(evJoin, s2);
    cudaStreamWaitEvent(0, evJoin, 0);

    spil_main<<<NPTS / PTS, 256, MN_TOTAL>>>(neighbor_features, theta_b);
    aux_gemm<1><<<NPTS / 128, 256, AX_TOTAL>>>(center_features, z_b, out);
}